// round 1
// baseline (speedup 1.0000x reference)
#include <cuda_runtime.h>
#include <cuda_bf16.h>
#include <cstdint>

// Problem: out[n, e] = tanh( sum_d input[n, d] * trans[urls[n], d, e] + bias[urls[n], e] )
// Shapes: input [16,256,256] fp32, urls [16,256] i32, trans [2000,256,256] fp32,
//         bias [2000,256] fp32. Output fp32 [16,256,256].
// N = 4096 tokens, D = 256.

#define D 256
#define N_TOKENS 4096

__global__ __launch_bounds__(256, 8)
void source_bias_seq_kernel(const float* __restrict__ inp,
                            const int*   __restrict__ urls,
                            const float* __restrict__ trans,
                            const float* __restrict__ bias,
                            float*       __restrict__ out)
{
    const int n = blockIdx.x;     // token index 0..4095
    const int e = threadIdx.x;    // output column 0..255

    __shared__ float xs[D];
    xs[e] = inp[(size_t)n * D + e];
    __syncthreads();

    const int u = urls[n];
    const float* __restrict__ T = trans + (size_t)u * D * D;

    float acc = bias[(size_t)u * D + e];

    // Row-major walk over d: each iteration the 256-thread CTA reads one
    // contiguous 1024B row of T. Unroll for memory-level parallelism;
    // split into 4 partial accumulators to relax the FFMA RAW chain.
    float a0 = 0.f, a1 = 0.f, a2 = 0.f, a3 = 0.f;
    #pragma unroll 4
    for (int d = 0; d < D; d += 4) {
        float t0 = T[(size_t)(d + 0) * D + e];
        float t1 = T[(size_t)(d + 1) * D + e];
        float t2 = T[(size_t)(d + 2) * D + e];
        float t3 = T[(size_t)(d + 3) * D + e];
        a0 = fmaf(xs[d + 0], t0, a0);
        a1 = fmaf(xs[d + 1], t1, a1);
        a2 = fmaf(xs[d + 2], t2, a2);
        a3 = fmaf(xs[d + 3], t3, a3);
    }
    acc += (a0 + a1) + (a2 + a3);

    out[(size_t)n * D + e] = tanhf(acc);
}

extern "C" void kernel_launch(void* const* d_in, const int* in_sizes, int n_in,
                              void* d_out, int out_size)
{
    const float* inp   = (const float*)d_in[0];
    const int*   urls  = (const int*)  d_in[1];
    const float* trans = (const float*)d_in[2];
    const float* bias  = (const float*)d_in[3];
    float*       out   = (float*)      d_out;

    source_bias_seq_kernel<<<N_TOKENS, D>>>(inp, urls, trans, bias, out);
}

// round 2
// speedup vs baseline: 1.1408x; 1.1408x over previous
#include <cuda_runtime.h>
#include <cuda_bf16.h>
#include <cstdint>

// out[n, e] = tanh( sum_d input[n, d] * trans[urls[n], d, e] + bias[urls[n], e] )
// input [16,256,256] f32, urls [16,256] i32, trans [2000,256,256] f32, bias [2000,256] f32.
//
// Strategy: group tokens by URL so each 256KB trans matrix is streamed from
// HBM once and applied to all tokens sharing it (expected ~1742 unique of
// 2000; traffic 1.02GB -> ~0.45GB).

#define D 256
#define N_TOKENS 4096
#define N_URLS 2000
#define CHUNK 8   // tokens processed per matrix stream

// ---- scratch (allocation-free: __device__ globals) ----
__device__ int g_counts[N_URLS];
__device__ int g_offsets[N_URLS];
__device__ int g_cursor[N_URLS];
__device__ int g_token_list[N_TOKENS];

// ---- 1) zero counters ----
__global__ void prep_zero_kernel() {
    int i = blockIdx.x * blockDim.x + threadIdx.x;
    if (i < N_URLS) { g_counts[i] = 0; g_cursor[i] = 0; }
}

// ---- 2) histogram of urls ----
__global__ void hist_kernel(const int* __restrict__ urls) {
    int n = blockIdx.x * blockDim.x + threadIdx.x;
    if (n < N_TOKENS) atomicAdd(&g_counts[urls[n]], 1);
}

// ---- 3) single-block exclusive scan over counts -> offsets ----
// 1024 threads, each owns 2 consecutive urls. Hillis-Steele over pair sums.
__global__ void scan_kernel() {
    __shared__ int sbuf[2][1024];
    int t = threadIdx.x;
    int i0 = 2 * t, i1 = 2 * t + 1;
    int c0 = (i0 < N_URLS) ? g_counts[i0] : 0;
    int c1 = (i1 < N_URLS) ? g_counts[i1] : 0;
    sbuf[0][t] = c0 + c1;
    __syncthreads();
    int src = 0;
    #pragma unroll
    for (int stride = 1; stride < 1024; stride <<= 1) {
        int v = sbuf[src][t];
        if (t >= stride) v += sbuf[src][t - stride];
        sbuf[src ^ 1][t] = v;
        src ^= 1;
        __syncthreads();
    }
    int incl = sbuf[src][t];            // inclusive scan of pair sums
    int excl = incl - (c0 + c1);        // exclusive prefix for url i0
    if (i0 < N_URLS) g_offsets[i0] = excl;
    if (i1 < N_URLS) g_offsets[i1] = excl + c0;
}

// ---- 4) scatter token indices into compacted per-url lists ----
__global__ void scatter_kernel(const int* __restrict__ urls) {
    int n = blockIdx.x * blockDim.x + threadIdx.x;
    if (n < N_TOKENS) {
        int u = urls[n];
        int pos = atomicAdd(&g_cursor[u], 1);
        g_token_list[g_offsets[u] + pos] = n;
    }
}

// ---- 5) main: one CTA per url, stream matrix once per <=CHUNK tokens ----
template<int K>
__device__ __forceinline__ void accum_and_store(
    const float* __restrict__ T, const float* __restrict__ xs_s,  // [CHUNK][D]
    const int* tok_s, float b, float* __restrict__ out, int e)
{
    float acc[K];
    #pragma unroll
    for (int kk = 0; kk < K; kk++) acc[kk] = 0.f;

    #pragma unroll 4
    for (int d = 0; d < D; d++) {
        float t = T[(size_t)d * D + e];
        #pragma unroll
        for (int kk = 0; kk < K; kk++)
            acc[kk] = fmaf(xs_s[kk * D + d], t, acc[kk]);
    }
    #pragma unroll
    for (int kk = 0; kk < K; kk++)
        out[(size_t)tok_s[kk] * D + e] = tanhf(acc[kk] + b);
}

__global__ __launch_bounds__(256)
void grouped_kernel(const float* __restrict__ inp,
                    const float* __restrict__ trans,
                    const float* __restrict__ bias,
                    float*       __restrict__ out)
{
    const int u = blockIdx.x;
    const int count = g_counts[u];
    if (count == 0) return;

    const int e = threadIdx.x;
    const int base_off = g_offsets[u];
    const float b = bias[(size_t)u * D + e];
    const float* __restrict__ T = trans + (size_t)u * D * D;

    __shared__ float xs_s[CHUNK * D];
    __shared__ int tok_s[CHUNK];

    for (int cbase = 0; cbase < count; cbase += CHUNK) {
        const int k = min(CHUNK, count - cbase);
        if (cbase) __syncthreads();  // protect smem reuse across chunks
        // load token ids + token vectors into smem
        if (e < k) tok_s[e] = g_token_list[base_off + cbase + e];
        __syncthreads();
        for (int kk = 0; kk < k; kk++)
            xs_s[kk * D + e] = inp[(size_t)tok_s[kk] * D + e];
        __syncthreads();

        switch (k) {
            case 1: accum_and_store<1>(T, xs_s, tok_s, b, out, e); break;
            case 2: accum_and_store<2>(T, xs_s, tok_s, b, out, e); break;
            case 3: accum_and_store<3>(T, xs_s, tok_s, b, out, e); break;
            case 4: accum_and_store<4>(T, xs_s, tok_s, b, out, e); break;
            case 5: accum_and_store<5>(T, xs_s, tok_s, b, out, e); break;
            case 6: accum_and_store<6>(T, xs_s, tok_s, b, out, e); break;
            case 7: accum_and_store<7>(T, xs_s, tok_s, b, out, e); break;
            default: accum_and_store<8>(T, xs_s, tok_s, b, out, e); break;
        }
    }
}

extern "C" void kernel_launch(void* const* d_in, const int* in_sizes, int n_in,
                              void* d_out, int out_size)
{
    const float* inp   = (const float*)d_in[0];
    const int*   urls  = (const int*)  d_in[1];
    const float* trans = (const float*)d_in[2];
    const float* bias  = (const float*)d_in[3];
    float*       out   = (float*)      d_out;

    prep_zero_kernel<<<(N_URLS + 255) / 256, 256>>>();
    hist_kernel<<<N_TOKENS / 256, 256>>>(urls);
    scan_kernel<<<1, 1024>>>();
    scatter_kernel<<<N_TOKENS / 256, 256>>>(urls);
    grouped_kernel<<<N_URLS, 256>>>(inp, trans, bias, out);
}

// round 3
// speedup vs baseline: 1.1787x; 1.0332x over previous
#include <cuda_runtime.h>
#include <cuda_bf16.h>
#include <cstdint>

// out[n, e] = tanh( sum_d input[n, d] * trans[urls[n], d, e] + bias[urls[n], e] )
// input [16,256,256] f32, urls [16,256] i32, trans [2000,256,256] f32, bias [2000,256] f32.
//
// v3: group tokens by URL (dedup matrix streams, ~446MB instead of 1.02GB),
//     split each matrix across 2 CTAs (column halves) for 2x CTA parallelism
//     and finer load balance, fuse all preprocessing into one single-CTA kernel.

#define D 256
#define HALF_D 128
#define N_TOKENS 4096
#define N_URLS 2000
#define CHUNK 8   // tokens processed per matrix stream

// ---- scratch (allocation-free: __device__ globals) ----
__device__ int g_counts[N_URLS];
__device__ int g_offsets[N_URLS];
__device__ int g_token_list[N_TOKENS];

// ---- fused prep: histogram + exclusive scan + scatter, one CTA ----
__global__ __launch_bounds__(1024)
void prep_kernel(const int* __restrict__ urls)
{
    __shared__ int s_cnt[N_URLS];
    __shared__ int s_off[N_URLS];
    __shared__ int s_cur[N_URLS];
    __shared__ int sbuf[2][1024];

    const int t = threadIdx.x;

    for (int i = t; i < N_URLS; i += 1024) { s_cnt[i] = 0; s_cur[i] = 0; }
    __syncthreads();

    for (int n = t; n < N_TOKENS; n += 1024)
        atomicAdd(&s_cnt[urls[n]], 1);
    __syncthreads();

    // exclusive scan: each thread owns 2 consecutive urls (Hillis-Steele on pair sums)
    const int i0 = 2 * t, i1 = 2 * t + 1;
    const int c0 = (i0 < N_URLS) ? s_cnt[i0] : 0;
    const int c1 = (i1 < N_URLS) ? s_cnt[i1] : 0;
    sbuf[0][t] = c0 + c1;
    __syncthreads();
    int src = 0;
    #pragma unroll
    for (int stride = 1; stride < 1024; stride <<= 1) {
        int v = sbuf[src][t];
        if (t >= stride) v += sbuf[src][t - stride];
        sbuf[src ^ 1][t] = v;
        src ^= 1;
        __syncthreads();
    }
    const int excl = sbuf[src][t] - (c0 + c1);
    if (i0 < N_URLS) {
        s_off[i0] = excl;
        g_offsets[i0] = excl;
        g_counts[i0] = c0;
    }
    if (i1 < N_URLS) {
        s_off[i1] = excl + c0;
        g_offsets[i1] = excl + c0;
        g_counts[i1] = c1;
    }
    __syncthreads();

    // scatter token ids into compacted per-url lists
    for (int n = t; n < N_TOKENS; n += 1024) {
        const int u = urls[n];
        const int pos = atomicAdd(&s_cur[u], 1);
        g_token_list[s_off[u] + pos] = n;
    }
}

// ---- main: 2 CTAs per url (column halves), stream matrix slice once per chunk ----
template<int K>
__device__ __forceinline__ void accum_and_store(
    const float* __restrict__ T, const float* __restrict__ xs_s,
    const int* tok_s, float b, float* __restrict__ out, int e)
{
    float acc[K];
    #pragma unroll
    for (int kk = 0; kk < K; kk++) acc[kk] = 0.f;

    #pragma unroll 8
    for (int d = 0; d < D; d++) {
        const float t = T[(size_t)d * D + e];
        #pragma unroll
        for (int kk = 0; kk < K; kk++)
            acc[kk] = fmaf(xs_s[kk * D + d], t, acc[kk]);
    }
    #pragma unroll
    for (int kk = 0; kk < K; kk++)
        out[(size_t)tok_s[kk] * D + e] = tanhf(acc[kk] + b);
}

__global__ __launch_bounds__(HALF_D)
void grouped_kernel(const float* __restrict__ inp,
                    const float* __restrict__ trans,
                    const float* __restrict__ bias,
                    float*       __restrict__ out)
{
    const int u     = blockIdx.x >> 1;
    const int count = g_counts[u];
    if (count == 0) return;

    const int half = blockIdx.x & 1;
    const int tl   = threadIdx.x;          // 0..127
    const int e    = half * HALF_D + tl;   // this CTA's output column

    const int base_off = g_offsets[u];
    const float b = bias[(size_t)u * D + e];
    const float* __restrict__ T = trans + (size_t)u * D * D;

    __shared__ float xs_s[CHUNK * D];
    __shared__ int tok_s[CHUNK];

    for (int cbase = 0; cbase < count; cbase += CHUNK) {
        const int k = min(CHUNK, count - cbase);
        if (cbase) __syncthreads();
        if (tl < k) tok_s[tl] = g_token_list[base_off + cbase + tl];
        __syncthreads();
        for (int kk = 0; kk < k; kk++) {
            xs_s[kk * D + tl]          = inp[(size_t)tok_s[kk] * D + tl];
            xs_s[kk * D + tl + HALF_D] = inp[(size_t)tok_s[kk] * D + tl + HALF_D];
        }
        __syncthreads();

        switch (k) {
            case 1: accum_and_store<1>(T, xs_s, tok_s, b, out, e); break;
            case 2: accum_and_store<2>(T, xs_s, tok_s, b, out, e); break;
            case 3: accum_and_store<3>(T, xs_s, tok_s, b, out, e); break;
            case 4: accum_and_store<4>(T, xs_s, tok_s, b, out, e); break;
            case 5: accum_and_store<5>(T, xs_s, tok_s, b, out, e); break;
            case 6: accum_and_store<6>(T, xs_s, tok_s, b, out, e); break;
            case 7: accum_and_store<7>(T, xs_s, tok_s, b, out, e); break;
            default: accum_and_store<8>(T, xs_s, tok_s, b, out, e); break;
        }
    }
}

extern "C" void kernel_launch(void* const* d_in, const int* in_sizes, int n_in,
                              void* d_out, int out_size)
{
    const float* inp   = (const float*)d_in[0];
    const int*   urls  = (const int*)  d_in[1];
    const float* trans = (const float*)d_in[2];
    const float* bias  = (const float*)d_in[3];
    float*       out   = (float*)      d_out;

    prep_kernel<<<1, 1024>>>(urls);
    grouped_kernel<<<2 * N_URLS, HALF_D>>>(inp, trans, bias, out);
}

// round 4
// speedup vs baseline: 1.2814x; 1.0871x over previous
#include <cuda_runtime.h>
#include <cuda_bf16.h>
#include <cstdint>

// out[n, e] = tanh( sum_d input[n, d] * trans[urls[n], d, e] + bias[urls[n], e] )
// input [16,256,256] f32, urls [16,256] i32, trans [2000,256,256] f32, bias [2000,256] f32.
//
// v4: URL-grouped dedup + float4 T loads (4 cols/thread) + 4 row-slices/CTA
//     with shuffle reduction. K (tokens per matrix pass) capped at 4 to keep
//     accumulators in registers. 2 CTAs per URL (column halves).

#define D 256
#define D4 64            // D/4 float4 per row
#define N_TOKENS 4096
#define N_URLS 2000
#define CHUNK 4          // tokens per matrix pass

// ---- scratch ----
__device__ int g_counts[N_URLS];
__device__ int g_offsets[N_URLS];
__device__ int g_token_list[N_TOKENS];

// ---- fused prep: histogram + scan + scatter, one CTA ----
__global__ __launch_bounds__(1024)
void prep_kernel(const int* __restrict__ urls)
{
    __shared__ int s_cnt[N_URLS];
    __shared__ int s_off[N_URLS];
    __shared__ int s_cur[N_URLS];
    __shared__ int sbuf[2][1024];

    const int t = threadIdx.x;
    for (int i = t; i < N_URLS; i += 1024) { s_cnt[i] = 0; s_cur[i] = 0; }
    __syncthreads();
    for (int n = t; n < N_TOKENS; n += 1024) atomicAdd(&s_cnt[urls[n]], 1);
    __syncthreads();

    const int i0 = 2 * t, i1 = 2 * t + 1;
    const int c0 = (i0 < N_URLS) ? s_cnt[i0] : 0;
    const int c1 = (i1 < N_URLS) ? s_cnt[i1] : 0;
    sbuf[0][t] = c0 + c1;
    __syncthreads();
    int src = 0;
    #pragma unroll
    for (int stride = 1; stride < 1024; stride <<= 1) {
        int v = sbuf[src][t];
        if (t >= stride) v += sbuf[src][t - stride];
        sbuf[src ^ 1][t] = v;
        src ^= 1;
        __syncthreads();
    }
    const int excl = sbuf[src][t] - (c0 + c1);
    if (i0 < N_URLS) { s_off[i0] = excl;      g_offsets[i0] = excl;      g_counts[i0] = c0; }
    if (i1 < N_URLS) { s_off[i1] = excl + c0; g_offsets[i1] = excl + c0; g_counts[i1] = c1; }
    __syncthreads();

    for (int n = t; n < N_TOKENS; n += 1024) {
        const int u = urls[n];
        const int pos = atomicAdd(&s_cur[u], 1);
        g_token_list[s_off[u] + pos] = n;
    }
}

// ---- main compute ----
// CTA: 128 threads = 32 column-groups (cg) x 4 row-slices (rs).
//   tid = cg*4 + rs  -> rs lives in lane bits [0:2) so shfl_xor reduces it.
// Thread (cg, rs) accumulates rows d = rs, rs+4, ..., 252 for float4 column
// group cidx = half*32 + cg of the gathered matrix.
template<int K>
__device__ __forceinline__ void accum_and_store(
    const float4* __restrict__ T4, const float* __restrict__ xs_s,
    const int* tok_s, const float4& bv, float4* __restrict__ out4,
    int cidx, int rs)
{
    float4 acc[K];
    #pragma unroll
    for (int kk = 0; kk < K; kk++) acc[kk] = make_float4(0.f, 0.f, 0.f, 0.f);

    #pragma unroll 4
    for (int d = rs; d < D; d += 4) {
        const float4 v = T4[d * D4 + cidx];
        #pragma unroll
        for (int kk = 0; kk < K; kk++) {
            const float x = xs_s[kk * D + d];
            acc[kk].x = fmaf(x, v.x, acc[kk].x);
            acc[kk].y = fmaf(x, v.y, acc[kk].y);
            acc[kk].z = fmaf(x, v.z, acc[kk].z);
            acc[kk].w = fmaf(x, v.w, acc[kk].w);
        }
    }

    // reduce the 4 row-slices (lane bits 0,1)
    #pragma unroll
    for (int kk = 0; kk < K; kk++) {
        #pragma unroll
        for (int s = 1; s <= 2; s <<= 1) {
            acc[kk].x += __shfl_xor_sync(0xffffffffu, acc[kk].x, s);
            acc[kk].y += __shfl_xor_sync(0xffffffffu, acc[kk].y, s);
            acc[kk].z += __shfl_xor_sync(0xffffffffu, acc[kk].z, s);
            acc[kk].w += __shfl_xor_sync(0xffffffffu, acc[kk].w, s);
        }
    }

    if (rs == 0) {
        #pragma unroll
        for (int kk = 0; kk < K; kk++) {
            float4 r;
            r.x = tanhf(acc[kk].x + bv.x);
            r.y = tanhf(acc[kk].y + bv.y);
            r.z = tanhf(acc[kk].z + bv.z);
            r.w = tanhf(acc[kk].w + bv.w);
            out4[(size_t)tok_s[kk] * D4 + cidx] = r;
        }
    }
}

__global__ __launch_bounds__(128, 10)
void grouped_kernel(const float4* __restrict__ inp4,
                    const float4* __restrict__ trans4,
                    const float4* __restrict__ bias4,
                    float4*       __restrict__ out4)
{
    const int u     = blockIdx.x >> 1;
    const int count = g_counts[u];
    if (count == 0) return;

    const int half = blockIdx.x & 1;
    const int tid  = threadIdx.x;
    const int cg   = tid >> 2;          // 0..31
    const int rs   = tid & 3;           // 0..3 (lane bits)
    const int cidx = half * 32 + cg;    // float4 column group 0..63

    const int base_off = g_offsets[u];
    const float4 bv = bias4[(size_t)u * D4 + cidx];
    const float4* __restrict__ T4 = trans4 + (size_t)u * D * D4;

    __shared__ float xs_s[CHUNK * D];
    __shared__ int tok_s[CHUNK];

    for (int cbase = 0; cbase < count; cbase += CHUNK) {
        const int k = min(CHUNK, count - cbase);
        if (cbase) __syncthreads();
        if (tid < k) tok_s[tid] = g_token_list[base_off + cbase + tid];
        __syncthreads();
        // load k token vectors (k*64 float4) with 128 threads
        for (int idx = tid; idx < k * D4; idx += 128) {
            const int kk = idx >> 6;            // idx / 64
            const int c  = idx & 63;
            reinterpret_cast<float4*>(xs_s)[kk * D4 + c] =
                inp4[(size_t)tok_s[kk] * D4 + c];
        }
        __syncthreads();

        switch (k) {
            case 1: accum_and_store<1>(T4, xs_s, tok_s, bv, out4, cidx, rs); break;
            case 2: accum_and_store<2>(T4, xs_s, tok_s, bv, out4, cidx, rs); break;
            case 3: accum_and_store<3>(T4, xs_s, tok_s, bv, out4, cidx, rs); break;
            default: accum_and_store<4>(T4, xs_s, tok_s, bv, out4, cidx, rs); break;
        }
    }
}

extern "C" void kernel_launch(void* const* d_in, const int* in_sizes, int n_in,
                              void* d_out, int out_size)
{
    const float4* inp4   = (const float4*)d_in[0];
    const int*    urls   = (const int*)   d_in[1];
    const float4* trans4 = (const float4*)d_in[2];
    const float4* bias4  = (const float4*)d_in[3];
    float4*       out4   = (float4*)      d_out;

    prep_kernel<<<1, 1024>>>(urls);
    grouped_kernel<<<2 * N_URLS, 128>>>(inp4, trans4, bias4, out4);
}